// round 15
// baseline (speedup 1.0000x reference)
#include <cuda_runtime.h>
#include <cuda_bf16.h>
#include <cstdint>

#define BB   8
#define NN   4096
#define CC   512
#define HH   256
#define NCLS 1000
#define MTOT (BB*NN)   // 32768

// ---------------- device scratch ----------------
__device__ __align__(16) __nv_bfloat16 g_featb[(size_t)MTOT * CC];  // 32 MB
__device__ __align__(16) __nv_bfloat16 g_Wb[(size_t)CC * CC];       // 512 KB

struct __align__(16) ZeroScratch {
    float prevsum[BB][CC];
    float v[BB][CC];
    float rowsum[MTOT];
    float rowsumsq[MTOT];
    float tb[BB];
    float Rb[BB];
    int   cnt[256];               // per-128-row-group completion counters
};
__device__ ZeroScratch g_zs;

__device__ __align__(16) float g_pooled[BB][CC];
__device__ __align__(16) float g_h1[BB][HH];
__device__ __align__(16) float g_h2[BB][HH];

// ---------------- front: cvt(feat) + cvt(W) ----------------
#define NB_CVTF 16384
#define NB_CVTW 256
#define NB_FRONT (NB_CVTF + NB_CVTW)

__global__ void __launch_bounds__(256)
k_front(const float* __restrict__ feat, const float* __restrict__ projW) {
    int blk = blockIdx.x;
    int t = threadIdx.x;
    if (blk < NB_CVTF) {
        int i = blk * 256 + t;
        float4 v = ((const float4*)feat)[i];
        ((__nv_bfloat162*)g_featb)[2 * i]     = __floats2bfloat162_rn(v.x, v.y);
        ((__nv_bfloat162*)g_featb)[2 * i + 1] = __floats2bfloat162_rn(v.z, v.w);
    } else {
        int i = (blk - NB_CVTF) * 256 + t;
        float4 v = ((const float4*)projW)[i];
        ((__nv_bfloat162*)g_Wb)[2 * i]     = __floats2bfloat162_rn(v.x, v.y);
        ((__nv_bfloat162*)g_Wb)[2 * i + 1] = __floats2bfloat162_rn(v.z, v.w);
    }
}

// ---------------- mega kernel: GEMM + prev + counter-gated vstats ----------
#define KC    32
#define NKC   16
#define STG   5
#define ROWB  80                      // 64B bf16 data + 16B pad
#define MATB  (128 * ROWB)            // 10240
#define STAGE_BYTES (2 * MATB)        // 20480
#define SMEM_NEED (STG * STAGE_BYTES + 512)
#define NB_GEMM 1024
#define NB_PREV 512
#define NB_VST  1024

__device__ __forceinline__ void ldsm4(uint32_t& r0, uint32_t& r1,
                                      uint32_t& r2, uint32_t& r3, uint32_t addr) {
    asm volatile("ldmatrix.sync.aligned.m8n8.x4.shared.b16 {%0,%1,%2,%3}, [%4];"
                 : "=r"(r0), "=r"(r1), "=r"(r2), "=r"(r3) : "r"(addr));
}

__global__ void __launch_bounds__(256, 2)
k_gemm(const float* __restrict__ pb, const float* __restrict__ prev,
       const float* __restrict__ feat) {
    extern __shared__ char sm[];
    const int tid = threadIdx.x;

    if (blockIdx.x >= NB_GEMM + NB_PREV) {
        // ---- vstats block (32 rows): waits for its rowgroup's 4 GEMM CTAs ----
        int v = blockIdx.x - NB_GEMM - NB_PREV;   // 0..1023
        int b = v >> 7;
        int n0 = (v & 127) * 32;
        int grp = (b * NN + n0) >> 7;             // 0..255

        if (tid == 0) {
            while (*(volatile int*)&g_zs.cnt[grp] < 4) __nanosleep(128);
        }
        __syncthreads();
        __threadfence();                          // acquire

        float* srstd = (float*)sm;
        float4* sh4 = (float4*)(sm + 128);
        if (tid < 32) {
            int r = b * NN + n0 + tid;
            float mu  = g_zs.rowsum[r] * (1.f / CC);
            float var = g_zs.rowsumsq[r] * (1.f / CC) - mu * mu;
            float rstd = rsqrtf(var + 1e-5f);
            srstd[tid] = rstd;
            float rm = rstd * mu;
#pragma unroll
            for (int off = 16; off > 0; off >>= 1) {
                rstd += __shfl_xor_sync(0xffffffffu, rstd, off);
                rm   += __shfl_xor_sync(0xffffffffu, rm, off);
            }
            if (tid == 0) {
                atomicAdd(&g_zs.Rb[b], rstd);
                atomicAdd(&g_zs.tb[b], rm);
            }
        }
        __syncthreads();

        int c4 = tid & 127;
        int rp = tid >> 7;
        const float4* p = (const float4*)(feat + ((size_t)(b * NN + n0 + rp)) * CC) + c4;
        float4 s = make_float4(0.f, 0.f, 0.f, 0.f);
#pragma unroll
        for (int i = 0; i < 16; i++) {
            float w = srstd[2 * i + rp];
            float4 vv = p[(size_t)i * 2 * (CC / 4)];
            s.x += w * vv.x; s.y += w * vv.y; s.z += w * vv.z; s.w += w * vv.w;
        }
        if (rp) sh4[c4] = s;
        __syncthreads();
        if (!rp) {
            float4 o = sh4[c4];
            atomicAdd(&g_zs.v[b][4 * c4 + 0], s.x + o.x);
            atomicAdd(&g_zs.v[b][4 * c4 + 1], s.y + o.y);
            atomicAdd(&g_zs.v[b][4 * c4 + 2], s.z + o.z);
            atomicAdd(&g_zs.v[b][4 * c4 + 3], s.w + o.w);
        }
        return;
    }

    if (blockIdx.x >= NB_GEMM) {
        // ---- prev column-sum block (64 rows) ----
        int id = blockIdx.x - NB_GEMM;            // 0..511
        int b = id >> 6;
        int n0 = (id & 63) * 64;
        int c4 = tid & 127;
        int rp = tid >> 7;
        const float4* p = (const float4*)(prev + ((size_t)(b * NN + n0 + rp)) * CC) + c4;
        float4 s = make_float4(0.f, 0.f, 0.f, 0.f);
#pragma unroll 8
        for (int i = 0; i < 32; i++) {
            float4 v = p[(size_t)i * 2 * (CC / 4)];
            s.x += v.x; s.y += v.y; s.z += v.z; s.w += v.w;
        }
        float4* sh = (float4*)sm;
        if (rp) sh[c4] = s;
        __syncthreads();
        if (!rp) {
            float4 o = sh[c4];
            atomicAdd(&g_zs.prevsum[b][4 * c4 + 0], s.x + o.x);
            atomicAdd(&g_zs.prevsum[b][4 * c4 + 1], s.y + o.y);
            atomicAdd(&g_zs.prevsum[b][4 * c4 + 2], s.z + o.z);
            atomicAdd(&g_zs.prevsum[b][4 * c4 + 3], s.w + o.w);
        }
        return;
    }

    // ---- GEMM block ----
    float* pbs = (float*)(sm + STG * STAGE_BYTES);
    const int rowblk = blockIdx.x >> 2;
    const int row0 = rowblk * 128;
    const int col0 = (blockIdx.x & 3) * 128;
    if (tid < 128) pbs[tid] = pb[col0 + tid];

    uint32_t sbase;
    asm("{ .reg .u64 t; cvta.to.shared.u64 t, %1; cvt.u32.u64 %0, t; }"
        : "=r"(sbase) : "l"(sm));

    auto fill = [&](int j) {
        int stg = j % STG;
        int k0 = j * KC;
        uint32_t ab = sbase + stg * STAGE_BYTES;
        uint32_t bb = ab + MATB;
#pragma unroll
        for (int i = 0; i < 2; i++) {
            int id = tid + i * 256;               // 0..511
            int r = id >> 2, seg = id & 3;
            const __nv_bfloat16* sa = g_featb + (size_t)(row0 + r) * CC + k0 + seg * 8;
            const __nv_bfloat16* sb = g_Wb   + (size_t)(col0 + r) * CC + k0 + seg * 8;
            asm volatile("cp.async.cg.shared.global [%0], [%1], 16;"
                         :: "r"(ab + r * ROWB + seg * 16), "l"(sa));
            asm volatile("cp.async.cg.shared.global [%0], [%1], 16;"
                         :: "r"(bb + r * ROWB + seg * 16), "l"(sb));
        }
    };

#pragma unroll
    for (int j = 0; j < STG - 1; j++) {
        fill(j);
        asm volatile("cp.async.commit_group;");
    }

    const int warp = tid >> 5, lane = tid & 31;
    const int g = lane >> 2, q = lane & 3;
    const int wm = warp >> 1, wn = warp & 1;
    const int rbase = wm * 32, cbase = wn * 64;

    const int lrow = lane & 7, lsel = lane >> 3;
    uint32_t offA0 = (uint32_t)((rbase + lrow + (lsel & 1) * 8) * ROWB + (lsel >> 1) * 16);
    uint32_t offA1 = offA0 + 16 * ROWB;
    uint32_t offB[4];
#pragma unroll
    for (int p = 0; p < 4; p++)
        offB[p] = (uint32_t)((cbase + (2 * p + (lsel >> 1)) * 8 + lrow) * ROWB
                             + (lsel & 1) * 16);

    float acc[2][8][4];
#pragma unroll
    for (int mt = 0; mt < 2; mt++)
#pragma unroll
        for (int nt = 0; nt < 8; nt++)
#pragma unroll
            for (int j = 0; j < 4; j++) acc[mt][nt][j] = 0.f;

    for (int kc = 0; kc < NKC; kc++) {
        asm volatile("cp.async.wait_group %0;" :: "n"(STG - 2));
        __syncthreads();
        // Issue next-stage loads immediately: target stage (kc+4)%5 is never a
        // stage any warp is reading this iteration (skew bounded by the bar).
        int jn = kc + STG - 1;
        if (jn < NKC) fill(jn);
        asm volatile("cp.async.commit_group;");

        uint32_t ab = sbase + (uint32_t)((kc % STG) * STAGE_BYTES);
        uint32_t bb = ab + MATB;
#pragma unroll
        for (int kt = 0; kt < 2; kt++) {
            uint32_t ko = kt * 32;
            uint32_t a[2][4], b[8][2];
            ldsm4(a[0][0], a[0][1], a[0][2], a[0][3], ab + offA0 + ko);
            ldsm4(a[1][0], a[1][1], a[1][2], a[1][3], ab + offA1 + ko);
#pragma unroll
            for (int p = 0; p < 4; p++)
                ldsm4(b[2 * p][0], b[2 * p][1], b[2 * p + 1][0], b[2 * p + 1][1],
                      bb + offB[p] + ko);
#pragma unroll
            for (int mt = 0; mt < 2; mt++)
#pragma unroll
                for (int nt = 0; nt < 8; nt++)
                    asm volatile(
                        "mma.sync.aligned.m16n8k16.row.col.f32.bf16.bf16.f32 "
                        "{%0,%1,%2,%3},{%4,%5,%6,%7},{%8,%9},{%0,%1,%2,%3};"
                        : "+f"(acc[mt][nt][0]), "+f"(acc[mt][nt][1]),
                          "+f"(acc[mt][nt][2]), "+f"(acc[mt][nt][3])
                        : "r"(a[mt][0]), "r"(a[mt][1]), "r"(a[mt][2]), "r"(a[mt][3]),
                          "r"(b[nt][0]), "r"(b[nt][1]));
        }
    }

#pragma unroll
    for (int mt = 0; mt < 2; mt++) {
        float s0 = 0.f, q0 = 0.f, s1 = 0.f, q1 = 0.f;
#pragma unroll
        for (int nt = 0; nt < 8; nt++) {
            float pb0 = pbs[cbase + nt * 8 + 2 * q];
            float pb1 = pbs[cbase + nt * 8 + 2 * q + 1];
            float v;
            v = acc[mt][nt][0] + pb0; s0 += v; q0 += v * v;
            v = acc[mt][nt][1] + pb1; s0 += v; q0 += v * v;
            v = acc[mt][nt][2] + pb0; s1 += v; q1 += v * v;
            v = acc[mt][nt][3] + pb1; s1 += v; q1 += v * v;
        }
#pragma unroll
        for (int off = 1; off < 4; off <<= 1) {
            s0 += __shfl_xor_sync(0xffffffffu, s0, off);
            q0 += __shfl_xor_sync(0xffffffffu, q0, off);
            s1 += __shfl_xor_sync(0xffffffffu, s1, off);
            q1 += __shfl_xor_sync(0xffffffffu, q1, off);
        }
        if (q == 0) {
            int r = row0 + rbase + mt * 16 + g;
            atomicAdd(&g_zs.rowsum[r],       s0);
            atomicAdd(&g_zs.rowsumsq[r],     q0);
            atomicAdd(&g_zs.rowsum[r + 8],   s1);
            atomicAdd(&g_zs.rowsumsq[r + 8], q1);
        }
    }

    // signal rowgroup completion (release)
    __threadfence();
    __syncthreads();
    if (tid == 0) atomicAdd(&g_zs.cnt[rowblk], 1);
}

// ---------------- tail GEMVs (proven warp-per-row, float4) ----------------
__device__ __forceinline__ float dot512(const float4* __restrict__ w4,
                                        const float4* __restrict__ x4, int lane) {
    float s = 0.f;
#pragma unroll
    for (int i = 0; i < 4; i++) {
        float4 a = w4[lane + 32 * i];
        float4 b = x4[lane + 32 * i];
        s += a.x * b.x + a.y * b.y + a.z * b.z + a.w * b.w;
    }
#pragma unroll
    for (int off = 16; off > 0; off >>= 1) s += __shfl_xor_sync(0xffffffffu, s, off);
    return s;
}
__device__ __forceinline__ float dot256(const float4* __restrict__ w4,
                                        const float4* __restrict__ x4, int lane) {
    float s = 0.f;
#pragma unroll
    for (int i = 0; i < 2; i++) {
        float4 a = w4[lane + 32 * i];
        float4 b = x4[lane + 32 * i];
        s += a.x * b.x + a.y * b.y + a.z * b.z + a.w * b.w;
    }
#pragma unroll
    for (int off = 16; off > 0; off >>= 1) s += __shfl_xor_sync(0xffffffffu, s, off);
    return s;
}

__global__ void k_pool(const float* __restrict__ W, const float* __restrict__ pb,
                       const float* __restrict__ lng, const float* __restrict__ lnb) {
    int warp = blockIdx.x * 8 + (threadIdx.x >> 5);   // 0..4095
    int lane = threadIdx.x & 31;
    int b = warp >> 9;
    int d = warp & 511;
    float s = dot512((const float4*)(W + (size_t)d * CC), (const float4*)g_zs.v[b], lane);
    if (lane == 0) {
        float sv = s + g_zs.Rb[b] * pb[d] - g_zs.tb[b];
        g_pooled[b][d] = (g_zs.prevsum[b][d] + lng[d] * sv) * (1.f / NN) + lnb[d];
    }
}

__global__ void k_mlp1(const float* __restrict__ W1, const float* __restrict__ b1) {
    int warp = blockIdx.x * 8 + (threadIdx.x >> 5);   // 0..2047
    int lane = threadIdx.x & 31;
    int b = warp >> 8, i = warp & 255;
    float s = dot512((const float4*)(W1 + (size_t)i * CC), (const float4*)g_pooled[b], lane);
    if (lane == 0) g_h1[b][i] = fmaxf(s + b1[i], 0.f);
}

__global__ void k_mlp2(const float* __restrict__ W2, const float* __restrict__ b2) {
    int warp = blockIdx.x * 8 + (threadIdx.x >> 5);
    int lane = threadIdx.x & 31;
    int b = warp >> 8, i = warp & 255;
    float s = dot256((const float4*)(W2 + (size_t)i * HH), (const float4*)g_h1[b], lane);
    if (lane == 0) g_h2[b][i] = fmaxf(s + b2[i], 0.f);
}

__global__ void k_mlp3(const float* __restrict__ W3, const float* __restrict__ b3,
                       float* __restrict__ out) {
    int warp = blockIdx.x * 8 + (threadIdx.x >> 5);   // 0..7999
    int lane = threadIdx.x & 31;
    int b = warp / NCLS, j = warp % NCLS;
    float s = dot256((const float4*)(W3 + (size_t)j * HH), (const float4*)g_h2[b], lane);
    if (lane == 0) out[b * NCLS + j] = s + b3[j];
}

// ---------------- launch ----------------
extern "C" void kernel_launch(void* const* d_in, const int* in_sizes, int n_in,
                              void* d_out, int out_size) {
    (void)in_sizes; (void)n_in; (void)out_size;
    const float* feat  = (const float*)d_in[0];
    const float* prev  = (const float*)d_in[1];
    // d_in[2], d_in[3] (positions) provably unused: gather is a row permutation
    // and all downstream consumers are permutation-invariant.
    const float* projW = (const float*)d_in[4];
    const float* projb = (const float*)d_in[5];
    const float* lng   = (const float*)d_in[6];
    const float* lnb   = (const float*)d_in[7];
    const float* W1    = (const float*)d_in[8];
    const float* b1    = (const float*)d_in[9];
    const float* W2    = (const float*)d_in[10];
    const float* b2    = (const float*)d_in[11];
    const float* W3    = (const float*)d_in[12];
    const float* b3    = (const float*)d_in[13];
    float* out = (float*)d_out;

    void* zs;
    cudaGetSymbolAddress(&zs, g_zs);

    cudaFuncSetAttribute(k_gemm, cudaFuncAttributeMaxDynamicSharedMemorySize,
                         SMEM_NEED);

    cudaMemsetAsync(zs, 0, sizeof(ZeroScratch));
    k_front<<<NB_FRONT, 256>>>(feat, projW);
    k_gemm<<<NB_GEMM + NB_PREV + NB_VST, 256, SMEM_NEED>>>(projb, prev, feat);
    k_pool<<<512, 256>>>(projW, projb, lng, lnb);
    k_mlp1<<<256, 256>>>(W1, b1);
    k_mlp2<<<256, 256>>>(W2, b2);
    k_mlp3<<<1000, 256>>>(W3, b3, out);
}

// round 16
// speedup vs baseline: 1.1163x; 1.1163x over previous
#include <cuda_runtime.h>
#include <cuda_bf16.h>
#include <cstdint>

#define BB   8
#define NN   4096
#define CC   512
#define HH   256
#define NCLS 1000
#define MTOT (BB*NN)   // 32768

// ---------------- device scratch ----------------
__device__ __align__(16) __nv_bfloat16 g_featb[(size_t)MTOT * CC];  // 32 MB
__device__ __align__(16) __nv_bfloat16 g_Wb[(size_t)CC * CC];       // 512 KB

struct __align__(16) ZeroScratch {
    float prevsum[BB][CC];
    float v[BB][CC];
    float rowsum[MTOT];
    float rowsumsq[MTOT];
    float tb[BB];
    float Rb[BB];
};
__device__ ZeroScratch g_zs;

__device__ __align__(16) float g_pooled[BB][CC];
__device__ __align__(16) float g_h1[BB][HH];
__device__ __align__(16) float g_h2[BB][HH];

// ---------------- front: zero scratch + cvt(feat) + cvt(W) ----------------
#define ZS_F4   ((int)(sizeof(ZeroScratch) / 16))
#define NB_ZERO 80                        // 80*256 = 20480 float4 slots >= ZS_F4
#define NB_CVTF 16384
#define NB_CVTW 256
#define NB_FRONT (NB_ZERO + NB_CVTF + NB_CVTW)

__global__ void __launch_bounds__(256)
k_front(const float* __restrict__ feat, const float* __restrict__ projW) {
    int blk = blockIdx.x;
    int t = threadIdx.x;
    if (blk < NB_ZERO) {
        int i = blk * 256 + t;
        if (i < ZS_F4) ((float4*)&g_zs)[i] = make_float4(0.f, 0.f, 0.f, 0.f);
        return;
    }
    blk -= NB_ZERO;
    if (blk < NB_CVTF) {
        int i = blk * 256 + t;
        float4 v = ((const float4*)feat)[i];
        ((__nv_bfloat162*)g_featb)[2 * i]     = __floats2bfloat162_rn(v.x, v.y);
        ((__nv_bfloat162*)g_featb)[2 * i + 1] = __floats2bfloat162_rn(v.z, v.w);
    } else {
        int i = (blk - NB_CVTF) * 256 + t;
        float4 v = ((const float4*)projW)[i];
        ((__nv_bfloat162*)g_Wb)[2 * i]     = __floats2bfloat162_rn(v.x, v.y);
        ((__nv_bfloat162*)g_Wb)[2 * i + 1] = __floats2bfloat162_rn(v.z, v.w);
    }
}

// ---------------- bf16 GEMM (ldmatrix) + prev appended ----------------
#define KC    32
#define NKC   16
#define STG   5
#define ROWB  80                      // 64B bf16 data + 16B pad
#define MATB  (128 * ROWB)            // 10240
#define STAGE_BYTES (2 * MATB)        // 20480
#define SMEM_NEED (STG * STAGE_BYTES + 512)
#define NB_GEMM 1024

__device__ __forceinline__ void ldsm4(uint32_t& r0, uint32_t& r1,
                                      uint32_t& r2, uint32_t& r3, uint32_t addr) {
    asm volatile("ldmatrix.sync.aligned.m8n8.x4.shared.b16 {%0,%1,%2,%3}, [%4];"
                 : "=r"(r0), "=r"(r1), "=r"(r2), "=r"(r3) : "r"(addr));
}

__global__ void __launch_bounds__(256, 2)
k_gemm(const float* __restrict__ pb, const float* __restrict__ prev) {
    extern __shared__ char sm[];
    const int tid = threadIdx.x;

    if (blockIdx.x >= NB_GEMM) {
        // ---- prev column-sum block (64 rows), appended after GEMM blocks ----
        int id = blockIdx.x - NB_GEMM;        // 0..511
        int b = id >> 6;
        int n0 = (id & 63) * 64;
        int c4 = tid & 127;
        int rp = tid >> 7;
        const float4* p = (const float4*)(prev + ((size_t)(b * NN + n0 + rp)) * CC) + c4;
        float4 s = make_float4(0.f, 0.f, 0.f, 0.f);
#pragma unroll 8
        for (int i = 0; i < 32; i++) {
            float4 v = p[(size_t)i * 2 * (CC / 4)];
            s.x += v.x; s.y += v.y; s.z += v.z; s.w += v.w;
        }
        float4* sh = (float4*)sm;
        if (rp) sh[c4] = s;
        __syncthreads();
        if (!rp) {
            float4 o = sh[c4];
            atomicAdd(&g_zs.prevsum[b][4 * c4 + 0], s.x + o.x);
            atomicAdd(&g_zs.prevsum[b][4 * c4 + 1], s.y + o.y);
            atomicAdd(&g_zs.prevsum[b][4 * c4 + 2], s.z + o.z);
            atomicAdd(&g_zs.prevsum[b][4 * c4 + 3], s.w + o.w);
        }
        return;
    }

    // ---- GEMM block ----
    float* pbs = (float*)(sm + STG * STAGE_BYTES);
    const int row0 = (blockIdx.x >> 2) * 128;
    const int col0 = (blockIdx.x & 3) * 128;
    if (tid < 128) pbs[tid] = pb[col0 + tid];

    uint32_t sbase;
    asm("{ .reg .u64 t; cvta.to.shared.u64 t, %1; cvt.u32.u64 %0, t; }"
        : "=r"(sbase) : "l"(sm));

    auto fill = [&](int j) {
        int stg = j % STG;
        int k0 = j * KC;
        uint32_t ab = sbase + stg * STAGE_BYTES;
        uint32_t bb = ab + MATB;
#pragma unroll
        for (int i = 0; i < 2; i++) {
            int id = tid + i * 256;           // 0..511
            int r = id >> 2, seg = id & 3;
            const __nv_bfloat16* sa = g_featb + (size_t)(row0 + r) * CC + k0 + seg * 8;
            const __nv_bfloat16* sb = g_Wb   + (size_t)(col0 + r) * CC + k0 + seg * 8;
            asm volatile("cp.async.cg.shared.global [%0], [%1], 16;"
                         :: "r"(ab + r * ROWB + seg * 16), "l"(sa));
            asm volatile("cp.async.cg.shared.global [%0], [%1], 16;"
                         :: "r"(bb + r * ROWB + seg * 16), "l"(sb));
        }
    };

#pragma unroll
    for (int j = 0; j < STG - 1; j++) {
        fill(j);
        asm volatile("cp.async.commit_group;");
    }

    const int warp = tid >> 5, lane = tid & 31;
    const int g = lane >> 2, q = lane & 3;
    const int wm = warp >> 1, wn = warp & 1;
    const int rbase = wm * 32, cbase = wn * 64;

    const int lrow = lane & 7, lsel = lane >> 3;
    uint32_t offA0 = (uint32_t)((rbase + lrow + (lsel & 1) * 8) * ROWB + (lsel >> 1) * 16);
    uint32_t offA1 = offA0 + 16 * ROWB;
    uint32_t offB[4];
#pragma unroll
    for (int p = 0; p < 4; p++)
        offB[p] = (uint32_t)((cbase + (2 * p + (lsel >> 1)) * 8 + lrow) * ROWB
                             + (lsel & 1) * 16);

    float acc[2][8][4];
#pragma unroll
    for (int mt = 0; mt < 2; mt++)
#pragma unroll
        for (int nt = 0; nt < 8; nt++)
#pragma unroll
            for (int j = 0; j < 4; j++) acc[mt][nt][j] = 0.f;

    for (int kc = 0; kc < NKC; kc++) {
        asm volatile("cp.async.wait_group %0;" :: "n"(STG - 2));
        __syncthreads();
        // Early fill: write target stage (kc+4)%5 is never the read stage
        // kc%5, and warp skew is bounded by the barrier above.
        int jn = kc + STG - 1;
        if (jn < NKC) fill(jn);
        asm volatile("cp.async.commit_group;");

        uint32_t ab = sbase + (uint32_t)((kc % STG) * STAGE_BYTES);
        uint32_t bb = ab + MATB;
#pragma unroll
        for (int kt = 0; kt < 2; kt++) {
            uint32_t ko = kt * 32;
            uint32_t a[2][4], b[8][2];
            ldsm4(a[0][0], a[0][1], a[0][2], a[0][3], ab + offA0 + ko);
            ldsm4(a[1][0], a[1][1], a[1][2], a[1][3], ab + offA1 + ko);
#pragma unroll
            for (int p = 0; p < 4; p++)
                ldsm4(b[2 * p][0], b[2 * p][1], b[2 * p + 1][0], b[2 * p + 1][1],
                      bb + offB[p] + ko);
#pragma unroll
            for (int mt = 0; mt < 2; mt++)
#pragma unroll
                for (int nt = 0; nt < 8; nt++)
                    asm volatile(
                        "mma.sync.aligned.m16n8k16.row.col.f32.bf16.bf16.f32 "
                        "{%0,%1,%2,%3},{%4,%5,%6,%7},{%8,%9},{%0,%1,%2,%3};"
                        : "+f"(acc[mt][nt][0]), "+f"(acc[mt][nt][1]),
                          "+f"(acc[mt][nt][2]), "+f"(acc[mt][nt][3])
                        : "r"(a[mt][0]), "r"(a[mt][1]), "r"(a[mt][2]), "r"(a[mt][3]),
                          "r"(b[nt][0]), "r"(b[nt][1]));
        }
    }

#pragma unroll
    for (int mt = 0; mt < 2; mt++) {
        float s0 = 0.f, q0 = 0.f, s1 = 0.f, q1 = 0.f;
#pragma unroll
        for (int nt = 0; nt < 8; nt++) {
            float pb0 = pbs[cbase + nt * 8 + 2 * q];
            float pb1 = pbs[cbase + nt * 8 + 2 * q + 1];
            float v;
            v = acc[mt][nt][0] + pb0; s0 += v; q0 += v * v;
            v = acc[mt][nt][1] + pb1; s0 += v; q0 += v * v;
            v = acc[mt][nt][2] + pb0; s1 += v; q1 += v * v;
            v = acc[mt][nt][3] + pb1; s1 += v; q1 += v * v;
        }
#pragma unroll
        for (int off = 1; off < 4; off <<= 1) {
            s0 += __shfl_xor_sync(0xffffffffu, s0, off);
            q0 += __shfl_xor_sync(0xffffffffu, q0, off);
            s1 += __shfl_xor_sync(0xffffffffu, s1, off);
            q1 += __shfl_xor_sync(0xffffffffu, q1, off);
        }
        if (q == 0) {
            int r = row0 + rbase + mt * 16 + g;
            atomicAdd(&g_zs.rowsum[r],       s0);
            atomicAdd(&g_zs.rowsumsq[r],     q0);
            atomicAdd(&g_zs.rowsum[r + 8],   s1);
            atomicAdd(&g_zs.rowsumsq[r + 8], q1);
        }
    }
}

// ---------------- fused: rstd + v = sum_n rstd*feat (32 rows/block) ----------------
__global__ void __launch_bounds__(256)
k_vstats(const float* __restrict__ feat) {
    int b = blockIdx.y;
    int n0 = blockIdx.x * 32;
    int t = threadIdx.x;

    __shared__ float srstd[32];
    if (t < 32) {
        int r = b * NN + n0 + t;
        float mu  = g_zs.rowsum[r] * (1.f / CC);
        float var = g_zs.rowsumsq[r] * (1.f / CC) - mu * mu;
        float rstd = rsqrtf(var + 1e-5f);
        srstd[t] = rstd;
        float rm = rstd * mu;
#pragma unroll
        for (int off = 16; off > 0; off >>= 1) {
            rstd += __shfl_xor_sync(0xffffffffu, rstd, off);
            rm   += __shfl_xor_sync(0xffffffffu, rm, off);
        }
        if (t == 0) {
            atomicAdd(&g_zs.Rb[b], rstd);
            atomicAdd(&g_zs.tb[b], rm);
        }
    }
    __syncthreads();

    int c4 = t & 127;
    int rp = t >> 7;
    const float4* p = (const float4*)(feat + ((size_t)(b * NN + n0 + rp)) * CC) + c4;
    float4 s = make_float4(0.f, 0.f, 0.f, 0.f);
#pragma unroll
    for (int i = 0; i < 16; i++) {
        float w = srstd[2 * i + rp];
        float4 v = p[(size_t)i * 2 * (CC / 4)];
        s.x += w * v.x; s.y += w * v.y; s.z += w * v.z; s.w += w * v.w;
    }
    __shared__ float4 sh[128];
    if (rp) sh[c4] = s;
    __syncthreads();
    if (!rp) {
        float4 o = sh[c4];
        atomicAdd(&g_zs.v[b][4 * c4 + 0], s.x + o.x);
        atomicAdd(&g_zs.v[b][4 * c4 + 1], s.y + o.y);
        atomicAdd(&g_zs.v[b][4 * c4 + 2], s.z + o.z);
        atomicAdd(&g_zs.v[b][4 * c4 + 3], s.w + o.w);
    }
}

// ---------------- tail GEMVs (proven warp-per-row, float4) ----------------
__device__ __forceinline__ float dot512(const float4* __restrict__ w4,
                                        const float4* __restrict__ x4, int lane) {
    float s = 0.f;
#pragma unroll
    for (int i = 0; i < 4; i++) {
        float4 a = w4[lane + 32 * i];
        float4 b = x4[lane + 32 * i];
        s += a.x * b.x + a.y * b.y + a.z * b.z + a.w * b.w;
    }
#pragma unroll
    for (int off = 16; off > 0; off >>= 1) s += __shfl_xor_sync(0xffffffffu, s, off);
    return s;
}
__device__ __forceinline__ float dot256(const float4* __restrict__ w4,
                                        const float4* __restrict__ x4, int lane) {
    float s = 0.f;
#pragma unroll
    for (int i = 0; i < 2; i++) {
        float4 a = w4[lane + 32 * i];
        float4 b = x4[lane + 32 * i];
        s += a.x * b.x + a.y * b.y + a.z * b.z + a.w * b.w;
    }
#pragma unroll
    for (int off = 16; off > 0; off >>= 1) s += __shfl_xor_sync(0xffffffffu, s, off);
    return s;
}

__global__ void k_pool(const float* __restrict__ W, const float* __restrict__ pb,
                       const float* __restrict__ lng, const float* __restrict__ lnb) {
    int warp = blockIdx.x * 8 + (threadIdx.x >> 5);   // 0..4095
    int lane = threadIdx.x & 31;
    int b = warp >> 9;
    int d = warp & 511;
    float s = dot512((const float4*)(W + (size_t)d * CC), (const float4*)g_zs.v[b], lane);
    if (lane == 0) {
        float sv = s + g_zs.Rb[b] * pb[d] - g_zs.tb[b];
        g_pooled[b][d] = (g_zs.prevsum[b][d] + lng[d] * sv) * (1.f / NN) + lnb[d];
    }
}

__global__ void k_mlp1(const float* __restrict__ W1, const float* __restrict__ b1) {
    int warp = blockIdx.x * 8 + (threadIdx.x >> 5);   // 0..2047
    int lane = threadIdx.x & 31;
    int b = warp >> 8, i = warp & 255;
    float s = dot512((const float4*)(W1 + (size_t)i * CC), (const float4*)g_pooled[b], lane);
    if (lane == 0) g_h1[b][i] = fmaxf(s + b1[i], 0.f);
}

__global__ void k_mlp2(const float* __restrict__ W2, const float* __restrict__ b2) {
    int warp = blockIdx.x * 8 + (threadIdx.x >> 5);
    int lane = threadIdx.x & 31;
    int b = warp >> 8, i = warp & 255;
    float s = dot256((const float4*)(W2 + (size_t)i * HH), (const float4*)g_h1[b], lane);
    if (lane == 0) g_h2[b][i] = fmaxf(s + b2[i], 0.f);
}

__global__ void k_mlp3(const float* __restrict__ W3, const float* __restrict__ b3,
                       float* __restrict__ out) {
    int warp = blockIdx.x * 8 + (threadIdx.x >> 5);   // 0..7999
    int lane = threadIdx.x & 31;
    int b = warp / NCLS, j = warp % NCLS;
    float s = dot256((const float4*)(W3 + (size_t)j * HH), (const float4*)g_h2[b], lane);
    if (lane == 0) out[b * NCLS + j] = s + b3[j];
}

// ---------------- launch ----------------
extern "C" void kernel_launch(void* const* d_in, const int* in_sizes, int n_in,
                              void* d_out, int out_size) {
    (void)in_sizes; (void)n_in; (void)out_size;
    const float* feat  = (const float*)d_in[0];
    const float* prev  = (const float*)d_in[1];
    // d_in[2], d_in[3] (positions) provably unused: gather is a row permutation
    // and all downstream consumers are permutation-invariant.
    const float* projW = (const float*)d_in[4];
    const float* projb = (const float*)d_in[5];
    const float* lng   = (const float*)d_in[6];
    const float* lnb   = (const float*)d_in[7];
    const float* W1    = (const float*)d_in[8];
    const float* b1    = (const float*)d_in[9];
    const float* W2    = (const float*)d_in[10];
    const float* b2    = (const float*)d_in[11];
    const float* W3    = (const float*)d_in[12];
    const float* b3    = (const float*)d_in[13];
    float* out = (float*)d_out;

    cudaFuncSetAttribute(k_gemm, cudaFuncAttributeMaxDynamicSharedMemorySize,
                         SMEM_NEED);

    k_front<<<NB_FRONT, 256>>>(feat, projW);
    k_gemm<<<NB_GEMM + 512, 256, SMEM_NEED>>>(projb, prev);
    k_vstats<<<dim3(128, 8), 256>>>(feat);
    k_pool<<<512, 256>>>(projW, projb, lng, lnb);
    k_mlp1<<<256, 256>>>(W1, b1);
    k_mlp2<<<256, 256>>>(W2, b2);
    k_mlp3<<<1000, 256>>>(W3, b3, out);
}